// round 6
// baseline (speedup 1.0000x reference)
#include <cuda_runtime.h>
#include <cstdint>

// ---------------------------------------------------------------------------
// XPool cross-modal attention, GB300 round 6: mma.sync tf32,
// 128x256 CTA tile, 8 warps x (64x64 warp tile), dynamic smem 51.2KB,
// conflict-free k-major smem (strides 136 / 264, both ≡ 8 mod 32).
// ---------------------------------------------------------------------------

#define EMBED 512
#define HEADS 2
#define HDIM  256
#define TTOK  4096
#define VTOK  768
#define FR    12
#define NV    64

#define SSTA 136          // A smem stride (words), 136 mod 32 == 8
#define SSTB 264          // B smem stride (words), 264 mod 32 == 8
#define SMEM_BYTES ((2*16*SSTA + 2*16*SSTB) * 4)   // 51200

// ------------------------------- scratch ----------------------------------
__device__ float g_tn  [TTOK*EMBED];
__device__ float g_vn  [VTOK*EMBED];
__device__ float g_q   [TTOK*EMBED];
__device__ float g_k   [VTOK*EMBED];
__device__ float g_v   [VTOK*EMBED];
__device__ float g_vt  [EMBED*VTOK];          // V transposed [512][768]
__device__ float g_s   [HEADS*TTOK*VTOK];     // logits/probs
__device__ float g_attn[TTOK*EMBED];
__device__ float g_opre[TTOK*EMBED];
__device__ float g_o   [TTOK*EMBED];
__device__ float g_lin [TTOK*EMBED];

__device__ __forceinline__ uint32_t f2tf32(float x) {
    uint32_t u;
    asm("cvt.rna.tf32.f32 %0, %1;" : "=r"(u) : "f"(x));
    return u;
}

// ---------------------------------------------------------------------------
// Core 128x256 NT tf32 GEMM tile body. 256 threads = 8 warps (2 x 4 of 64x64).
// C[i,j] = alpha * sum_k A[i,k]*B[j,k] (+ bias[j]).
// ---------------------------------------------------------------------------
__device__ __forceinline__ void gemm_tile_body(
    const float* __restrict__ A, int lda,
    const float* __restrict__ B, int ldb,
    float* __restrict__ C, int ldc,
    const float* __restrict__ bias,
    float alpha, int K, int bm, int bn)
{
    extern __shared__ uint32_t smem[];
    uint32_t (*As)[16][SSTA] = (uint32_t (*)[16][SSTA])smem;
    uint32_t (*Bs)[16][SSTB] = (uint32_t (*)[16][SSTB])(smem + 2*16*SSTA);

    const int tid  = threadIdx.x;
    const int lane = tid & 31;
    const int warp = tid >> 5;
    const int wm   = (warp >> 2) * 64;   // 2 row-warps x 64
    const int wn   = (warp & 3) * 64;    // 4 col-warps x 64
    const int gid  = lane >> 2;          // 0..7
    const int tig  = lane & 3;           // 0..3

    // A producer: row = tid&127, k-half = (tid>>7)*8  (8 floats/thread)
    const int parow = tid & 127;
    const int pakh  = (tid >> 7) * 8;
    // B producer: row = tid, all 16 k (16 floats/thread)
    const float* Ap = A + (size_t)(bm + parow) * lda + pakh;
    const float* Bp = B + (size_t)(bn + tid) * ldb;

    float acc[4][8][4];
#pragma unroll
    for (int mi = 0; mi < 4; mi++)
#pragma unroll
        for (int ni = 0; ni < 8; ni++)
#pragma unroll
            for (int r = 0; r < 4; r++) acc[mi][ni][r] = 0.0f;

    const int nsteps = K / 16;

    // stage 0 fill
    {
        float4 a0 = *(const float4*)(Ap);
        float4 a1 = *(const float4*)(Ap + 4);
        As[0][pakh+0][parow] = f2tf32(a0.x); As[0][pakh+1][parow] = f2tf32(a0.y);
        As[0][pakh+2][parow] = f2tf32(a0.z); As[0][pakh+3][parow] = f2tf32(a0.w);
        As[0][pakh+4][parow] = f2tf32(a1.x); As[0][pakh+5][parow] = f2tf32(a1.y);
        As[0][pakh+6][parow] = f2tf32(a1.z); As[0][pakh+7][parow] = f2tf32(a1.w);
#pragma unroll
        for (int j = 0; j < 4; j++) {
            float4 b = *(const float4*)(Bp + j * 4);
            Bs[0][j*4+0][tid] = f2tf32(b.x); Bs[0][j*4+1][tid] = f2tf32(b.y);
            Bs[0][j*4+2][tid] = f2tf32(b.z); Bs[0][j*4+3][tid] = f2tf32(b.w);
        }
    }
    __syncthreads();

#pragma unroll 1
    for (int step = 0; step < nsteps; step++) {
        const int cur = step & 1;
        const int nxt = cur ^ 1;
        const bool has_next = (step + 1) < nsteps;

        float4 a0, a1, pb[4];
        if (has_next) {
            const float* ap = Ap + (step + 1) * 16;
            const float* bp = Bp + (step + 1) * 16;
            a0 = *(const float4*)(ap);
            a1 = *(const float4*)(ap + 4);
#pragma unroll
            for (int j = 0; j < 4; j++) pb[j] = *(const float4*)(bp + j * 4);
        }

#pragma unroll
        for (int kk = 0; kk < 2; kk++) {
            const int kb = kk * 8;
            uint32_t af[4][4];
#pragma unroll
            for (int mi = 0; mi < 4; mi++) {
                const int r0 = wm + mi * 16 + gid;
                af[mi][0] = As[cur][kb + tig    ][r0];
                af[mi][1] = As[cur][kb + tig    ][r0 + 8];
                af[mi][2] = As[cur][kb + tig + 4][r0];
                af[mi][3] = As[cur][kb + tig + 4][r0 + 8];
            }
            uint32_t bf[8][2];
#pragma unroll
            for (int ni = 0; ni < 8; ni++) {
                const int n0 = wn + ni * 8 + gid;
                bf[ni][0] = Bs[cur][kb + tig    ][n0];
                bf[ni][1] = Bs[cur][kb + tig + 4][n0];
            }
#pragma unroll
            for (int mi = 0; mi < 4; mi++)
#pragma unroll
                for (int ni = 0; ni < 8; ni++) {
                    asm("mma.sync.aligned.m16n8k8.row.col.f32.tf32.tf32.f32 "
                        "{%0,%1,%2,%3}, {%4,%5,%6,%7}, {%8,%9}, {%0,%1,%2,%3};"
                        : "+f"(acc[mi][ni][0]), "+f"(acc[mi][ni][1]),
                          "+f"(acc[mi][ni][2]), "+f"(acc[mi][ni][3])
                        : "r"(af[mi][0]), "r"(af[mi][1]),
                          "r"(af[mi][2]), "r"(af[mi][3]),
                          "r"(bf[ni][0]), "r"(bf[ni][1]));
                }
        }

        if (has_next) {
            As[nxt][pakh+0][parow] = f2tf32(a0.x); As[nxt][pakh+1][parow] = f2tf32(a0.y);
            As[nxt][pakh+2][parow] = f2tf32(a0.z); As[nxt][pakh+3][parow] = f2tf32(a0.w);
            As[nxt][pakh+4][parow] = f2tf32(a1.x); As[nxt][pakh+5][parow] = f2tf32(a1.y);
            As[nxt][pakh+6][parow] = f2tf32(a1.z); As[nxt][pakh+7][parow] = f2tf32(a1.w);
#pragma unroll
            for (int j = 0; j < 4; j++) {
                Bs[nxt][j*4+0][tid] = f2tf32(pb[j].x);
                Bs[nxt][j*4+1][tid] = f2tf32(pb[j].y);
                Bs[nxt][j*4+2][tid] = f2tf32(pb[j].z);
                Bs[nxt][j*4+3][tid] = f2tf32(pb[j].w);
            }
            __syncthreads();
        }
    }

    // epilogue
#pragma unroll
    for (int mi = 0; mi < 4; mi++) {
        const int r0 = bm + wm + mi * 16 + gid;
#pragma unroll
        for (int ni = 0; ni < 8; ni++) {
            const int c0 = bn + wn + ni * 8 + tig * 2;
            float bx = 0.0f, by = 0.0f;
            if (bias) { bx = bias[c0]; by = bias[c0 + 1]; }
            float2 v0, v1;
            v0.x = alpha * acc[mi][ni][0] + bx;
            v0.y = alpha * acc[mi][ni][1] + by;
            v1.x = alpha * acc[mi][ni][2] + bx;
            v1.y = alpha * acc[mi][ni][3] + by;
            *(float2*)(C + (size_t)r0 * ldc + c0)       = v0;
            *(float2*)(C + (size_t)(r0 + 8) * ldc + c0) = v1;
        }
    }
}

// Generic z-batched NT GEMM (z strides may be pointer differences).
__global__ __launch_bounds__(256, 1) void mma_gemm(
    const float* __restrict__ A, int lda, long zA,
    const float* __restrict__ B, int ldb, long zB,
    float* __restrict__ C, int ldc, long zC,
    const float* __restrict__ bias, long zBias,
    float alpha, int K)
{
    A += (long)blockIdx.z * zA;
    B += (long)blockIdx.z * zB;
    C += (long)blockIdx.z * zC;
    if (bias) bias += (long)blockIdx.z * zBias;
    gemm_tile_body(A, lda, B, ldb, C, ldc, bias, alpha, K,
                   blockIdx.y * 128, blockIdx.x * 256);
}

// All three input projections in one launch: z=0 Q (M=4096), z=1 K, z=2 V.
__global__ __launch_bounds__(256, 1) void proj3_gemm(
    const float* __restrict__ tn, const float* __restrict__ vn,
    const float* __restrict__ Wq, const float* __restrict__ Wk,
    const float* __restrict__ Wv,
    const float* __restrict__ bq, const float* __restrict__ bk,
    const float* __restrict__ bv,
    float* __restrict__ q, float* __restrict__ k, float* __restrict__ v)
{
    const int z  = blockIdx.z;
    const int bm = blockIdx.y * 128;
    if (z > 0 && bm >= VTOK) return;
    const float* A = (z == 0) ? tn : vn;
    const float* B = (z == 0) ? Wq : (z == 1) ? Wk : Wv;
    const float* bias = (z == 0) ? bq : (z == 1) ? bk : bv;
    float* C = (z == 0) ? q : (z == 1) ? k : v;
    gemm_tile_body(A, EMBED, B, EMBED, C, EMBED, bias, 1.0f, EMBED,
                   bm, blockIdx.x * 256);
}

// ---------------------------------------------------------------------------
// LayerNorm (optionally fused residual add). One block per row.
// ---------------------------------------------------------------------------
__global__ __launch_bounds__(128) void ln_kernel(
    const float* __restrict__ x, const float* __restrict__ addx,
    const float* __restrict__ g, const float* __restrict__ b,
    float* __restrict__ out)
{
    const int row = blockIdx.x;
    const int t = threadIdx.x;
    const float* xr = x + (size_t)row * EMBED;

    float v[4];
#pragma unroll
    for (int i = 0; i < 4; i++) {
        float val = xr[t + i * 128];
        if (addx) val += addx[(size_t)row * EMBED + t + i * 128];
        v[i] = val;
    }
    float s  = v[0] + v[1] + v[2] + v[3];
    float s2 = v[0]*v[0] + v[1]*v[1] + v[2]*v[2] + v[3]*v[3];
#pragma unroll
    for (int o = 16; o > 0; o >>= 1) {
        s  += __shfl_xor_sync(0xffffffffu, s,  o);
        s2 += __shfl_xor_sync(0xffffffffu, s2, o);
    }
    __shared__ float ss[4], ss2[4];
    const int w = t >> 5, l = t & 31;
    if (l == 0) { ss[w] = s; ss2[w] = s2; }
    __syncthreads();
    s  = ss[0] + ss[1] + ss[2] + ss[3];
    s2 = ss2[0] + ss2[1] + ss2[2] + ss2[3];

    const float mu   = s * (1.0f / EMBED);
    const float var  = s2 * (1.0f / EMBED) - mu * mu;
    const float rstd = rsqrtf(var + 1e-5f);
#pragma unroll
    for (int i = 0; i < 4; i++) {
        const int c = t + i * 128;
        out[(size_t)row * EMBED + c] = (v[i] - mu) * rstd * g[c] + b[c];
    }
}

// ---------------------------------------------------------------------------
// Per-(video,head,token) softmax over 12 contiguous frames.
// ---------------------------------------------------------------------------
__global__ __launch_bounds__(256) void softmax_kernel(float* __restrict__ S, int ngroups)
{
    const int g = blockIdx.x * blockDim.x + threadIdx.x;
    if (g >= ngroups) return;
    float* p = S + (size_t)g * FR;
    float v[FR];
    float m = -3.0e38f;
#pragma unroll
    for (int i = 0; i < FR; i++) { v[i] = p[i]; m = fmaxf(m, v[i]); }
    float sum = 0.0f;
#pragma unroll
    for (int i = 0; i < FR; i++) { v[i] = __expf(v[i] - m); sum += v[i]; }
    const float inv = 1.0f / sum;
#pragma unroll
    for (int i = 0; i < FR; i++) p[i] = v[i] * inv;
}

// ---------------------------------------------------------------------------
// Transpose V [768][512] -> Vt [512][768]
// ---------------------------------------------------------------------------
__global__ __launch_bounds__(256) void transpose_kernel(
    const float* __restrict__ in, float* __restrict__ out)
{
    __shared__ float t[32][33];
    const int x  = blockIdx.x * 32 + threadIdx.x;
    const int y0 = blockIdx.y * 32;
#pragma unroll
    for (int i = threadIdx.y; i < 32; i += 8)
        t[i][threadIdx.x] = in[(size_t)(y0 + i) * EMBED + x];
    __syncthreads();
    const int ox  = y0 + threadIdx.x;
    const int oy0 = blockIdx.x * 32;
#pragma unroll
    for (int i = threadIdx.y; i < 32; i += 8)
        out[(size_t)(oy0 + i) * VTOK + ox] = t[threadIdx.x][i];
}

// ---------------------------------------------------------------------------
extern "C" void kernel_launch(void* const* d_in, const int* in_sizes, int n_in,
                              void* d_out, int out_size)
{
    const float* text  = (const float*)d_in[0];
    const float* video = (const float*)d_in[1];
    const float* ln1_g = (const float*)d_in[2];
    const float* ln1_b = (const float*)d_in[3];
    const float* Wq = (const float*)d_in[4];
    const float* bq = (const float*)d_in[5];
    const float* Wk = (const float*)d_in[6];
    const float* bk = (const float*)d_in[7];
    const float* Wv = (const float*)d_in[8];
    const float* bv = (const float*)d_in[9];
    const float* Wo = (const float*)d_in[10];
    const float* bo = (const float*)d_in[11];
    const float* Wl = (const float*)d_in[12];
    const float* bl = (const float*)d_in[13];
    const float* ln2_g = (const float*)d_in[14];
    const float* ln2_b = (const float*)d_in[15];
    const float* ln3_g = (const float*)d_in[16];
    const float* ln3_b = (const float*)d_in[17];
    float* out = (float*)d_out;

    cudaFuncSetAttribute(mma_gemm,
        cudaFuncAttributeMaxDynamicSharedMemorySize, SMEM_BYTES);
    cudaFuncSetAttribute(proj3_gemm,
        cudaFuncAttributeMaxDynamicSharedMemorySize, SMEM_BYTES);

    float *tn, *vn, *q, *k, *v, *vt, *s, *attn, *opre, *o, *lin;
    cudaGetSymbolAddress((void**)&tn,   g_tn);
    cudaGetSymbolAddress((void**)&vn,   g_vn);
    cudaGetSymbolAddress((void**)&q,    g_q);
    cudaGetSymbolAddress((void**)&k,    g_k);
    cudaGetSymbolAddress((void**)&v,    g_v);
    cudaGetSymbolAddress((void**)&vt,   g_vt);
    cudaGetSymbolAddress((void**)&s,    g_s);
    cudaGetSymbolAddress((void**)&attn, g_attn);
    cudaGetSymbolAddress((void**)&opre, g_opre);
    cudaGetSymbolAddress((void**)&o,    g_o);
    cudaGetSymbolAddress((void**)&lin,  g_lin);

    // 1) shared LN1
    ln_kernel<<<TTOK, 128>>>(text,  nullptr, ln1_g, ln1_b, tn);
    ln_kernel<<<VTOK, 128>>>(video, nullptr, ln1_g, ln1_b, vn);

    // 2) Q/K/V projections in one launch (N=512 -> 2 tiles of 256)
    proj3_gemm<<<dim3(2, 32, 3), 256, SMEM_BYTES>>>(tn, vn, Wq, Wk, Wv,
                                                    bq, bk, bv, q, k, v);

    // 3) transpose V
    transpose_kernel<<<dim3(16, 24), dim3(32, 8)>>>(v, vt);

    // 4) logits: S_h = Q_h @ K_h^T / 16, heads on z (N=768 -> 3 tiles)
    mma_gemm<<<dim3(3, 32, 2), 256, SMEM_BYTES>>>(
        q, EMBED, HDIM, k, EMBED, HDIM,
        s, VTOK, (long)TTOK * VTOK, nullptr, 0, 1.0f / 16.0f, HDIM);

    // 5) per-video frame softmax
    softmax_kernel<<<(HEADS * TTOK * NV + 255) / 256, 256>>>(s, HEADS * TTOK * NV);

    // 6) attn_h = P_h @ V_h / 64 (N=256 -> 1 tile)
    mma_gemm<<<dim3(1, 32, 2), 256, SMEM_BYTES>>>(
        s, VTOK, (long)TTOK * VTOK, vt, VTOK, (long)HDIM * VTOK,
        attn, EMBED, HDIM, nullptr, 0, 1.0f / 64.0f, VTOK);

    // 7) output projection + LN2
    mma_gemm<<<dim3(2, 32, 1), 256, SMEM_BYTES>>>(attn, EMBED, 0, Wo, EMBED, 0,
                                                  opre, EMBED, 0, bo, 0, 1.0f, EMBED);
    ln_kernel<<<TTOK, 128>>>(opre, nullptr, ln2_g, ln2_b, o);

    // 8) linear + residual + LN3
    mma_gemm<<<dim3(2, 32, 1), 256, SMEM_BYTES>>>(o, EMBED, 0, Wl, EMBED, 0,
                                                  lin, EMBED, 0, bl, 0, 1.0f, EMBED);
    ln_kernel<<<TTOK, 128>>>(o, lin, ln3_g, ln3_b, out);
}

// round 7
// speedup vs baseline: 1.1758x; 1.1758x over previous
#include <cuda_runtime.h>
#include <cstdint>

// ---------------------------------------------------------------------------
// XPool cross-modal attention, GB300 round 7: mma.sync tf32.
// R5 config (128x128 CTA tile, 8 warps x 32x64, 2 CTAs/SM) + paired-uint2
// SMEM layout: element pair (k, k+4) stored together so fragment loads are
// LDS.64 and producer stores are STS.64 (halves LSU instruction count).
// ---------------------------------------------------------------------------

#define EMBED 512
#define HEADS 2
#define HDIM  256
#define TTOK  4096
#define VTOK  768
#define FR    12
#define NV    64

#define SST2 136   // uint2 stride; 136 mod 16 == 8 -> conflict-free phases

// ------------------------------- scratch ----------------------------------
__device__ float g_tn  [TTOK*EMBED];
__device__ float g_vn  [VTOK*EMBED];
__device__ float g_q   [TTOK*EMBED];
__device__ float g_k   [VTOK*EMBED];
__device__ float g_v   [VTOK*EMBED];
__device__ float g_vt  [EMBED*VTOK];          // V transposed [512][768]
__device__ float g_s   [HEADS*TTOK*VTOK];     // logits/probs
__device__ float g_attn[TTOK*EMBED];
__device__ float g_opre[TTOK*EMBED];
__device__ float g_o   [TTOK*EMBED];
__device__ float g_lin [TTOK*EMBED];

__device__ __forceinline__ uint32_t f2tf32(float x) {
    uint32_t u;
    asm("cvt.rna.tf32.f32 %0, %1;" : "=r"(u) : "f"(x));
    return u;
}

// ---------------------------------------------------------------------------
// Core 128x128 NT tf32 GEMM tile body. 256 threads = 8 warps (4x2 of 32x64).
// C[i,j] = alpha * sum_k A[i,k]*B[j,k] (+ bias[j]).
// SMEM layout: X2[buf][octet*4 + tig][row] = (tf32(x[k]), tf32(x[k+4]))
// where k = octet*8 + tig. Fragments load uint2; producers store uint2.
// ---------------------------------------------------------------------------
__device__ __forceinline__ void gemm_tile_body(
    const float* __restrict__ A, int lda,
    const float* __restrict__ B, int ldb,
    float* __restrict__ C, int ldc,
    const float* __restrict__ bias,
    float alpha, int K, int bm, int bn,
    uint2 (*As2)[8][SST2], uint2 (*Bs2)[8][SST2])
{
    const int tid  = threadIdx.x;
    const int lane = tid & 31;
    const int warp = tid >> 5;
    const int wm   = (warp >> 1) * 32;   // 4 row-warps x 32
    const int wn   = (warp & 1) * 64;    // 2 col-warps x 64
    const int gid  = lane >> 2;          // 0..7
    const int tig  = lane & 3;           // 0..3

    // producer: row = tid&127, octet = tid>>7 (8 consecutive k per thread)
    const int prow = tid & 127;
    const int poct = tid >> 7;
    const float* Ap = A + (size_t)(bm + prow) * lda + poct * 8;
    const float* Bp = B + (size_t)(bn + prow) * ldb + poct * 8;

    float acc[2][8][4];
#pragma unroll
    for (int mi = 0; mi < 2; mi++)
#pragma unroll
        for (int ni = 0; ni < 8; ni++)
#pragma unroll
            for (int r = 0; r < 4; r++) acc[mi][ni][r] = 0.0f;

    const int nsteps = K / 16;

    // stage 0 fill
    {
        float4 a0 = *(const float4*)(Ap);
        float4 a1 = *(const float4*)(Ap + 4);
        float4 b0 = *(const float4*)(Bp);
        float4 b1 = *(const float4*)(Bp + 4);
        uint2 q;
        q.x = f2tf32(a0.x); q.y = f2tf32(a1.x); As2[0][poct*4+0][prow] = q;
        q.x = f2tf32(a0.y); q.y = f2tf32(a1.y); As2[0][poct*4+1][prow] = q;
        q.x = f2tf32(a0.z); q.y = f2tf32(a1.z); As2[0][poct*4+2][prow] = q;
        q.x = f2tf32(a0.w); q.y = f2tf32(a1.w); As2[0][poct*4+3][prow] = q;
        q.x = f2tf32(b0.x); q.y = f2tf32(b1.x); Bs2[0][poct*4+0][prow] = q;
        q.x = f2tf32(b0.y); q.y = f2tf32(b1.y); Bs2[0][poct*4+1][prow] = q;
        q.x = f2tf32(b0.z); q.y = f2tf32(b1.z); Bs2[0][poct*4+2][prow] = q;
        q.x = f2tf32(b0.w); q.y = f2tf32(b1.w); Bs2[0][poct*4+3][prow] = q;
    }
    __syncthreads();

#pragma unroll 1
    for (int step = 0; step < nsteps; step++) {
        const int cur = step & 1;
        const int nxt = cur ^ 1;
        const bool has_next = (step + 1) < nsteps;

        float4 a0, a1, b0, b1;
        if (has_next) {
            const float* ap = Ap + (step + 1) * 16;
            const float* bp = Bp + (step + 1) * 16;
            a0 = *(const float4*)(ap);
            a1 = *(const float4*)(ap + 4);
            b0 = *(const float4*)(bp);
            b1 = *(const float4*)(bp + 4);
        }

#pragma unroll
        for (int kk = 0; kk < 2; kk++) {
            const int krow = kk * 4 + tig;
            uint32_t af[2][4];
#pragma unroll
            for (int mi = 0; mi < 2; mi++) {
                const int r0 = wm + mi * 16 + gid;
                uint2 lo = As2[cur][krow][r0];
                uint2 hi = As2[cur][krow][r0 + 8];
                af[mi][0] = lo.x; af[mi][1] = hi.x;
                af[mi][2] = lo.y; af[mi][3] = hi.y;
            }
            uint32_t bf[8][2];
#pragma unroll
            for (int ni = 0; ni < 8; ni++) {
                uint2 q = Bs2[cur][krow][wn + ni * 8 + gid];
                bf[ni][0] = q.x; bf[ni][1] = q.y;
            }
#pragma unroll
            for (int mi = 0; mi < 2; mi++)
#pragma unroll
                for (int ni = 0; ni < 8; ni++) {
                    asm("mma.sync.aligned.m16n8k8.row.col.f32.tf32.tf32.f32 "
                        "{%0,%1,%2,%3}, {%4,%5,%6,%7}, {%8,%9}, {%0,%1,%2,%3};"
                        : "+f"(acc[mi][ni][0]), "+f"(acc[mi][ni][1]),
                          "+f"(acc[mi][ni][2]), "+f"(acc[mi][ni][3])
                        : "r"(af[mi][0]), "r"(af[mi][1]),
                          "r"(af[mi][2]), "r"(af[mi][3]),
                          "r"(bf[ni][0]), "r"(bf[ni][1]));
                }
        }

        if (has_next) {
            uint2 q;
            q.x = f2tf32(a0.x); q.y = f2tf32(a1.x); As2[nxt][poct*4+0][prow] = q;
            q.x = f2tf32(a0.y); q.y = f2tf32(a1.y); As2[nxt][poct*4+1][prow] = q;
            q.x = f2tf32(a0.z); q.y = f2tf32(a1.z); As2[nxt][poct*4+2][prow] = q;
            q.x = f2tf32(a0.w); q.y = f2tf32(a1.w); As2[nxt][poct*4+3][prow] = q;
            q.x = f2tf32(b0.x); q.y = f2tf32(b1.x); Bs2[nxt][poct*4+0][prow] = q;
            q.x = f2tf32(b0.y); q.y = f2tf32(b1.y); Bs2[nxt][poct*4+1][prow] = q;
            q.x = f2tf32(b0.z); q.y = f2tf32(b1.z); Bs2[nxt][poct*4+2][prow] = q;
            q.x = f2tf32(b0.w); q.y = f2tf32(b1.w); Bs2[nxt][poct*4+3][prow] = q;
            __syncthreads();
        }
    }

    // epilogue: c0,c1 at (row, 2*tig), c2,c3 at (row+8, 2*tig)
#pragma unroll
    for (int mi = 0; mi < 2; mi++) {
        const int r0 = bm + wm + mi * 16 + gid;
#pragma unroll
        for (int ni = 0; ni < 8; ni++) {
            const int c0 = bn + wn + ni * 8 + tig * 2;
            float bx = 0.0f, by = 0.0f;
            if (bias) { bx = bias[c0]; by = bias[c0 + 1]; }
            float2 v0, v1;
            v0.x = alpha * acc[mi][ni][0] + bx;
            v0.y = alpha * acc[mi][ni][1] + by;
            v1.x = alpha * acc[mi][ni][2] + bx;
            v1.y = alpha * acc[mi][ni][3] + by;
            *(float2*)(C + (size_t)r0 * ldc + c0)       = v0;
            *(float2*)(C + (size_t)(r0 + 8) * ldc + c0) = v1;
        }
    }
}

// Generic z-batched NT GEMM (z strides may be pointer differences).
__global__ __launch_bounds__(256, 2) void mma_gemm(
    const float* __restrict__ A, int lda, long zA,
    const float* __restrict__ B, int ldb, long zB,
    float* __restrict__ C, int ldc, long zC,
    const float* __restrict__ bias, long zBias,
    float alpha, int K)
{
    __shared__ uint2 As2[2][8][SST2];
    __shared__ uint2 Bs2[2][8][SST2];
    A += (long)blockIdx.z * zA;
    B += (long)blockIdx.z * zB;
    C += (long)blockIdx.z * zC;
    if (bias) bias += (long)blockIdx.z * zBias;
    gemm_tile_body(A, lda, B, ldb, C, ldc, bias, alpha, K,
                   blockIdx.y * 128, blockIdx.x * 128, As2, Bs2);
}

// All three input projections in one launch: z=0 Q (M=4096), z=1 K, z=2 V.
__global__ __launch_bounds__(256, 2) void proj3_gemm(
    const float* __restrict__ tn, const float* __restrict__ vn,
    const float* __restrict__ Wq, const float* __restrict__ Wk,
    const float* __restrict__ Wv,
    const float* __restrict__ bq, const float* __restrict__ bk,
    const float* __restrict__ bv,
    float* __restrict__ q, float* __restrict__ k, float* __restrict__ v)
{
    __shared__ uint2 As2[2][8][SST2];
    __shared__ uint2 Bs2[2][8][SST2];
    const int z  = blockIdx.z;
    const int bm = blockIdx.y * 128;
    if (z > 0 && bm >= VTOK) return;
    const float* A = (z == 0) ? tn : vn;
    const float* B = (z == 0) ? Wq : (z == 1) ? Wk : Wv;
    const float* bias = (z == 0) ? bq : (z == 1) ? bk : bv;
    float* C = (z == 0) ? q : (z == 1) ? k : v;
    gemm_tile_body(A, EMBED, B, EMBED, C, EMBED, bias, 1.0f, EMBED,
                   bm, blockIdx.x * 128, As2, Bs2);
}

// ---------------------------------------------------------------------------
// LayerNorm (optionally fused residual add). One block per row.
// ---------------------------------------------------------------------------
__global__ __launch_bounds__(128) void ln_kernel(
    const float* __restrict__ x, const float* __restrict__ addx,
    const float* __restrict__ g, const float* __restrict__ b,
    float* __restrict__ out)
{
    const int row = blockIdx.x;
    const int t = threadIdx.x;
    const float* xr = x + (size_t)row * EMBED;

    float v[4];
#pragma unroll
    for (int i = 0; i < 4; i++) {
        float val = xr[t + i * 128];
        if (addx) val += addx[(size_t)row * EMBED + t + i * 128];
        v[i] = val;
    }
    float s  = v[0] + v[1] + v[2] + v[3];
    float s2 = v[0]*v[0] + v[1]*v[1] + v[2]*v[2] + v[3]*v[3];
#pragma unroll
    for (int o = 16; o > 0; o >>= 1) {
        s  += __shfl_xor_sync(0xffffffffu, s,  o);
        s2 += __shfl_xor_sync(0xffffffffu, s2, o);
    }
    __shared__ float ss[4], ss2[4];
    const int w = t >> 5, l = t & 31;
    if (l == 0) { ss[w] = s; ss2[w] = s2; }
    __syncthreads();
    s  = ss[0] + ss[1] + ss[2] + ss[3];
    s2 = ss2[0] + ss2[1] + ss2[2] + ss2[3];

    const float mu   = s * (1.0f / EMBED);
    const float var  = s2 * (1.0f / EMBED) - mu * mu;
    const float rstd = rsqrtf(var + 1e-5f);
#pragma unroll
    for (int i = 0; i < 4; i++) {
        const int c = t + i * 128;
        out[(size_t)row * EMBED + c] = (v[i] - mu) * rstd * g[c] + b[c];
    }
}

// ---------------------------------------------------------------------------
// Per-(video,head,token) softmax over 12 contiguous frames.
// ---------------------------------------------------------------------------
__global__ __launch_bounds__(256) void softmax_kernel(float* __restrict__ S, int ngroups)
{
    const int g = blockIdx.x * blockDim.x + threadIdx.x;
    if (g >= ngroups) return;
    float* p = S + (size_t)g * FR;
    float v[FR];
    float m = -3.0e38f;
#pragma unroll
    for (int i = 0; i < FR; i++) { v[i] = p[i]; m = fmaxf(m, v[i]); }
    float sum = 0.0f;
#pragma unroll
    for (int i = 0; i < FR; i++) { v[i] = __expf(v[i] - m); sum += v[i]; }
    const float inv = 1.0f / sum;
#pragma unroll
    for (int i = 0; i < FR; i++) p[i] = v[i] * inv;
}

// ---------------------------------------------------------------------------
// Transpose V [768][512] -> Vt [512][768]
// ---------------------------------------------------------------------------
__global__ __launch_bounds__(256) void transpose_kernel(
    const float* __restrict__ in, float* __restrict__ out)
{
    __shared__ float t[32][33];
    const int x  = blockIdx.x * 32 + threadIdx.x;
    const int y0 = blockIdx.y * 32;
#pragma unroll
    for (int i = threadIdx.y; i < 32; i += 8)
        t[i][threadIdx.x] = in[(size_t)(y0 + i) * EMBED + x];
    __syncthreads();
    const int ox  = y0 + threadIdx.x;
    const int oy0 = blockIdx.x * 32;
#pragma unroll
    for (int i = threadIdx.y; i < 32; i += 8)
        out[(size_t)(oy0 + i) * VTOK + ox] = t[threadIdx.x][i];
}

// ---------------------------------------------------------------------------
extern "C" void kernel_launch(void* const* d_in, const int* in_sizes, int n_in,
                              void* d_out, int out_size)
{
    const float* text  = (const float*)d_in[0];
    const float* video = (const float*)d_in[1];
    const float* ln1_g = (const float*)d_in[2];
    const float* ln1_b = (const float*)d_in[3];
    const float* Wq = (const float*)d_in[4];
    const float* bq = (const float*)d_in[5];
    const float* Wk = (const float*)d_in[6];
    const float* bk = (const float*)d_in[7];
    const float* Wv = (const float*)d_in[8];
    const float* bv = (const float*)d_in[9];
    const float* Wo = (const float*)d_in[10];
    const float* bo = (const float*)d_in[11];
    const float* Wl = (const float*)d_in[12];
    const float* bl = (const float*)d_in[13];
    const float* ln2_g = (const float*)d_in[14];
    const float* ln2_b = (const float*)d_in[15];
    const float* ln3_g = (const float*)d_in[16];
    const float* ln3_b = (const float*)d_in[17];
    float* out = (float*)d_out;

    float *tn, *vn, *q, *k, *v, *vt, *s, *attn, *opre, *o, *lin;
    cudaGetSymbolAddress((void**)&tn,   g_tn);
    cudaGetSymbolAddress((void**)&vn,   g_vn);
    cudaGetSymbolAddress((void**)&q,    g_q);
    cudaGetSymbolAddress((void**)&k,    g_k);
    cudaGetSymbolAddress((void**)&v,    g_v);
    cudaGetSymbolAddress((void**)&vt,   g_vt);
    cudaGetSymbolAddress((void**)&s,    g_s);
    cudaGetSymbolAddress((void**)&attn, g_attn);
    cudaGetSymbolAddress((void**)&opre, g_opre);
    cudaGetSymbolAddress((void**)&o,    g_o);
    cudaGetSymbolAddress((void**)&lin,  g_lin);

    // 1) shared LN1
    ln_kernel<<<TTOK, 128>>>(text,  nullptr, ln1_g, ln1_b, tn);
    ln_kernel<<<VTOK, 128>>>(video, nullptr, ln1_g, ln1_b, vn);

    // 2) Q/K/V projections in one launch
    proj3_gemm<<<dim3(4, 32, 3), 256>>>(tn, vn, Wq, Wk, Wv, bq, bk, bv, q, k, v);

    // 3) transpose V
    transpose_kernel<<<dim3(16, 24), dim3(32, 8)>>>(v, vt);

    // 4) logits: S_h = Q_h @ K_h^T / 16, heads on z
    mma_gemm<<<dim3(6, 32, 2), 256>>>(
        q, EMBED, HDIM, k, EMBED, HDIM,
        s, VTOK, (long)TTOK * VTOK, nullptr, 0, 1.0f / 16.0f, HDIM);

    // 5) per-video frame softmax
    softmax_kernel<<<(HEADS * TTOK * NV + 255) / 256, 256>>>(s, HEADS * TTOK * NV);

    // 6) attn_h = P_h @ V_h / 64
    mma_gemm<<<dim3(2, 32, 2), 256>>>(
        s, VTOK, (long)TTOK * VTOK, vt, VTOK, (long)HDIM * VTOK,
        attn, EMBED, HDIM, nullptr, 0, 1.0f / 64.0f, VTOK);

    // 7) output projection + LN2
    mma_gemm<<<dim3(4, 32, 1), 256>>>(attn, EMBED, 0, Wo, EMBED, 0,
                                      opre, EMBED, 0, bo, 0, 1.0f, EMBED);
    ln_kernel<<<TTOK, 128>>>(opre, nullptr, ln2_g, ln2_b, o);

    // 8) linear + residual + LN3
    mma_gemm<<<dim3(4, 32, 1), 256>>>(o, EMBED, 0, Wl, EMBED, 0,
                                      lin, EMBED, 0, bl, 0, 1.0f, EMBED);
    ln_kernel<<<TTOK, 128>>>(o, lin, ln3_g, ln3_b, out);
}

// round 8
// speedup vs baseline: 1.5692x; 1.3346x over previous
#include <cuda_runtime.h>
#include <cstdint>

// ---------------------------------------------------------------------------
// XPool cross-modal attention, GB300 round 8: mma.sync tf32 + cp.async.
// All GEMM inputs are pre-rounded to tf32 in gmem (producers round), so the
// GEMM uses a 4-stage cp.async (LDGSTS) pipeline with no cvt/STS in the loop.
// 128x128 CTA tile, 8 warps x (32x64), row-major smem [row][20] conflict-free.
// ---------------------------------------------------------------------------

#define EMBED 512
#define HEADS 2
#define HDIM  256
#define TTOK  4096
#define VTOK  768
#define FR    12
#define NV    64

#define APAD   20                     // smem row pitch in words
#define STG_W  (128 * APAD)           // words per stage per matrix (2560)
#define NSTAGE 4
#define SMEM_BYTES (2 * NSTAGE * STG_W * 4)   // 81920

// ------------------------------- scratch ----------------------------------
__device__ float g_tn  [TTOK*EMBED];
__device__ float g_vn  [VTOK*EMBED];
__device__ float g_q   [TTOK*EMBED];
__device__ float g_k   [VTOK*EMBED];
__device__ float g_v   [VTOK*EMBED];
__device__ float g_vt  [EMBED*VTOK];
__device__ float g_s   [HEADS*TTOK*VTOK];
__device__ float g_attn[TTOK*EMBED];
__device__ float g_opre[TTOK*EMBED];
__device__ float g_o   [TTOK*EMBED];
__device__ float g_or  [TTOK*EMBED];          // tf32-rounded copy of o
__device__ float g_lin [TTOK*EMBED];
__device__ float g_wqr [EMBED*EMBED];
__device__ float g_wkr [EMBED*EMBED];
__device__ float g_wvr [EMBED*EMBED];
__device__ float g_wor [EMBED*EMBED];
__device__ float g_wlr [EMBED*EMBED];

__device__ __forceinline__ uint32_t f2tf32(float x) {
    uint32_t u;
    asm("cvt.rna.tf32.f32 %0, %1;" : "=r"(u) : "f"(x));
    return u;
}
__device__ __forceinline__ float roundtf(float x) {
    return __uint_as_float(f2tf32(x));
}

#define CP16(dst, src) \
    asm volatile("cp.async.cg.shared.global [%0], [%1], 16;" \
        :: "r"(dst), "l"(src) : "memory")
#define CP_COMMIT() asm volatile("cp.async.commit_group;" ::: "memory")
#define CP_WAIT2()  asm volatile("cp.async.wait_group 2;" ::: "memory")
#define CP_WAIT0()  asm volatile("cp.async.wait_group 0;" ::: "memory")

// ---------------------------------------------------------------------------
// 128x128 NT tf32 GEMM, inputs pre-rounded to tf32 in gmem.
// C[i,j] = alpha * sum_k A[i,k]*B[j,k] (+bias[j]); roundC rounds the output.
// ---------------------------------------------------------------------------
__device__ __forceinline__ void gemm_tile_body(
    const float* __restrict__ A, int lda,
    const float* __restrict__ B, int ldb,
    float* __restrict__ C, int ldc,
    const float* __restrict__ bias,
    float alpha, int K, int bm, int bn, int roundC)
{
    extern __shared__ uint32_t sm[];
    uint32_t* Asw = sm;                       // [NSTAGE][128][APAD]
    uint32_t* Bsw = sm + NSTAGE * STG_W;

    const int tid  = threadIdx.x;
    const int lane = tid & 31;
    const int warp = tid >> 5;
    const int wm   = (warp >> 1) * 32;
    const int wn   = (warp & 1) * 64;
    const int gid  = lane >> 2;
    const int tig  = lane & 3;

    // producer: row = tid&127, 8-float half = (tid>>7)*8, two 16B chunks
    const int prow = tid & 127;
    const int pkc  = (tid >> 7) * 8;
    const float* Ap = A + (size_t)(bm + prow) * lda + pkc;
    const float* Bp = B + (size_t)(bn + prow) * ldb + pkc;

    const uint32_t aBase = (uint32_t)__cvta_generic_to_shared(Asw)
                         + (uint32_t)(prow * APAD + pkc) * 4u;
    const uint32_t bBase = (uint32_t)__cvta_generic_to_shared(Bsw)
                         + (uint32_t)(prow * APAD + pkc) * 4u;

    float acc[2][8][4];
#pragma unroll
    for (int mi = 0; mi < 2; mi++)
#pragma unroll
        for (int ni = 0; ni < 8; ni++)
#pragma unroll
            for (int r = 0; r < 4; r++) acc[mi][ni][r] = 0.0f;

    const int nsteps = K / 16;

    // prologue: stages 0..2
#pragma unroll
    for (int s = 0; s < NSTAGE - 1; s++) {
        const uint32_t ad = aBase + (uint32_t)(s * STG_W) * 4u;
        const uint32_t bd = bBase + (uint32_t)(s * STG_W) * 4u;
        CP16(ad,      Ap + s * 16);
        CP16(ad + 16, Ap + s * 16 + 4);
        CP16(bd,      Bp + s * 16);
        CP16(bd + 16, Bp + s * 16 + 4);
        CP_COMMIT();
    }

#pragma unroll 1
    for (int step = 0; step < nsteps; step++) {
        const int cur = step & (NSTAGE - 1);
        CP_WAIT2();
        __syncthreads();

        const uint32_t* Ac = Asw + cur * STG_W;
        const uint32_t* Bc = Bsw + cur * STG_W;

#pragma unroll
        for (int kk = 0; kk < 2; kk++) {
            const int kb = kk * 8;
            uint32_t af[2][4];
#pragma unroll
            for (int mi = 0; mi < 2; mi++) {
                const int r0 = (wm + mi * 16 + gid) * APAD;
                af[mi][0] = Ac[r0 + kb + tig];
                af[mi][1] = Ac[r0 + 8 * APAD + kb + tig];
                af[mi][2] = Ac[r0 + kb + tig + 4];
                af[mi][3] = Ac[r0 + 8 * APAD + kb + tig + 4];
            }
            uint32_t bf[8][2];
#pragma unroll
            for (int ni = 0; ni < 8; ni++) {
                const int n0 = (wn + ni * 8 + gid) * APAD;
                bf[ni][0] = Bc[n0 + kb + tig];
                bf[ni][1] = Bc[n0 + kb + tig + 4];
            }
#pragma unroll
            for (int mi = 0; mi < 2; mi++)
#pragma unroll
                for (int ni = 0; ni < 8; ni++) {
                    asm("mma.sync.aligned.m16n8k8.row.col.f32.tf32.tf32.f32 "
                        "{%0,%1,%2,%3}, {%4,%5,%6,%7}, {%8,%9}, {%0,%1,%2,%3};"
                        : "+f"(acc[mi][ni][0]), "+f"(acc[mi][ni][1]),
                          "+f"(acc[mi][ni][2]), "+f"(acc[mi][ni][3])
                        : "r"(af[mi][0]), "r"(af[mi][1]),
                          "r"(af[mi][2]), "r"(af[mi][3]),
                          "r"(bf[ni][0]), "r"(bf[ni][1]));
                }
        }

        const int pf = step + NSTAGE - 1;
        if (pf < nsteps) {
            const int ps = pf & (NSTAGE - 1);
            const uint32_t ad = aBase + (uint32_t)(ps * STG_W) * 4u;
            const uint32_t bd = bBase + (uint32_t)(ps * STG_W) * 4u;
            CP16(ad,      Ap + pf * 16);
            CP16(ad + 16, Ap + pf * 16 + 4);
            CP16(bd,      Bp + pf * 16);
            CP16(bd + 16, Bp + pf * 16 + 4);
        }
        CP_COMMIT();
    }
    CP_WAIT0();

    // epilogue
#pragma unroll
    for (int mi = 0; mi < 2; mi++) {
        const int r0 = bm + wm + mi * 16 + gid;
#pragma unroll
        for (int ni = 0; ni < 8; ni++) {
            const int c0 = bn + wn + ni * 8 + tig * 2;
            float bx = 0.0f, by = 0.0f;
            if (bias) { bx = bias[c0]; by = bias[c0 + 1]; }
            float2 v0, v1;
            v0.x = alpha * acc[mi][ni][0] + bx;
            v0.y = alpha * acc[mi][ni][1] + by;
            v1.x = alpha * acc[mi][ni][2] + bx;
            v1.y = alpha * acc[mi][ni][3] + by;
            if (roundC) {
                v0.x = roundtf(v0.x); v0.y = roundtf(v0.y);
                v1.x = roundtf(v1.x); v1.y = roundtf(v1.y);
            }
            *(float2*)(C + (size_t)r0 * ldc + c0)       = v0;
            *(float2*)(C + (size_t)(r0 + 8) * ldc + c0) = v1;
        }
    }
}

__global__ __launch_bounds__(256, 2) void mma_gemm(
    const float* __restrict__ A, int lda, long zA,
    const float* __restrict__ B, int ldb, long zB,
    float* __restrict__ C, int ldc, long zC,
    const float* __restrict__ bias, long zBias,
    float alpha, int K, int roundC)
{
    A += (long)blockIdx.z * zA;
    B += (long)blockIdx.z * zB;
    C += (long)blockIdx.z * zC;
    if (bias) bias += (long)blockIdx.z * zBias;
    gemm_tile_body(A, lda, B, ldb, C, ldc, bias, alpha, K,
                   blockIdx.y * 128, blockIdx.x * 128, roundC);
}

// z=0: Q (M=4096), z=1: K, z=2: V (M=768). q,k rounded; v full (transpose rounds).
__global__ __launch_bounds__(256, 2) void proj3_gemm(
    const float* __restrict__ tn, const float* __restrict__ vn,
    const float* __restrict__ Wq, const float* __restrict__ Wk,
    const float* __restrict__ Wv,
    const float* __restrict__ bq, const float* __restrict__ bk,
    const float* __restrict__ bv,
    float* __restrict__ q, float* __restrict__ k, float* __restrict__ v)
{
    const int z  = blockIdx.z;
    const int bm = blockIdx.y * 128;
    if (z > 0 && bm >= VTOK) return;
    const float* A = (z == 0) ? tn : vn;
    const float* B = (z == 0) ? Wq : (z == 1) ? Wk : Wv;
    const float* bias = (z == 0) ? bq : (z == 1) ? bk : bv;
    float* C = (z == 0) ? q : (z == 1) ? k : v;
    gemm_tile_body(A, EMBED, B, EMBED, C, EMBED, bias, 1.0f, EMBED,
                   bm, blockIdx.x * 128, z < 2 ? 1 : 0);
}

// ---------------------------------------------------------------------------
// Round 5 weight matrices to tf32 (one shot).
// ---------------------------------------------------------------------------
__global__ __launch_bounds__(256) void roundw_kernel(
    const float* __restrict__ w0, const float* __restrict__ w1,
    const float* __restrict__ w2, const float* __restrict__ w3,
    const float* __restrict__ w4,
    float* __restrict__ o0, float* __restrict__ o1,
    float* __restrict__ o2, float* __restrict__ o3,
    float* __restrict__ o4)
{
    const int i = blockIdx.x * 256 + threadIdx.x;
    const int z = blockIdx.y;
    const float* w = (z == 0) ? w0 : (z == 1) ? w1 : (z == 2) ? w2
                   : (z == 3) ? w3 : w4;
    float* o = (z == 0) ? o0 : (z == 1) ? o1 : (z == 2) ? o2
             : (z == 3) ? o3 : o4;
    float4 x = *(const float4*)(w + i * 4);
    float4 y;
    y.x = roundtf(x.x); y.y = roundtf(x.y);
    y.z = roundtf(x.z); y.w = roundtf(x.w);
    *(float4*)(o + i * 4) = y;
}

// ---------------------------------------------------------------------------
// LayerNorm. round_main: round primary output to tf32. out_r: optional
// additional rounded copy (primary stays full precision).
// ---------------------------------------------------------------------------
__global__ __launch_bounds__(128) void ln_kernel(
    const float* __restrict__ x, const float* __restrict__ addx,
    const float* __restrict__ g, const float* __restrict__ b,
    float* __restrict__ out, float* __restrict__ out_r, int round_main)
{
    const int row = blockIdx.x;
    const int t = threadIdx.x;
    const float* xr = x + (size_t)row * EMBED;

    float v[4];
#pragma unroll
    for (int i = 0; i < 4; i++) {
        float val = xr[t + i * 128];
        if (addx) val += addx[(size_t)row * EMBED + t + i * 128];
        v[i] = val;
    }
    float s  = v[0] + v[1] + v[2] + v[3];
    float s2 = v[0]*v[0] + v[1]*v[1] + v[2]*v[2] + v[3]*v[3];
#pragma unroll
    for (int o = 16; o > 0; o >>= 1) {
        s  += __shfl_xor_sync(0xffffffffu, s,  o);
        s2 += __shfl_xor_sync(0xffffffffu, s2, o);
    }
    __shared__ float ss[4], ss2[4];
    const int w = t >> 5, l = t & 31;
    if (l == 0) { ss[w] = s; ss2[w] = s2; }
    __syncthreads();
    s  = ss[0] + ss[1] + ss[2] + ss[3];
    s2 = ss2[0] + ss2[1] + ss2[2] + ss2[3];

    const float mu   = s * (1.0f / EMBED);
    const float var  = s2 * (1.0f / EMBED) - mu * mu;
    const float rstd = rsqrtf(var + 1e-5f);
#pragma unroll
    for (int i = 0; i < 4; i++) {
        const int c = t + i * 128;
        float y = (v[i] - mu) * rstd * g[c] + b[c];
        out[(size_t)row * EMBED + c] = round_main ? roundtf(y) : y;
        if (out_r) out_r[(size_t)row * EMBED + c] = roundtf(y);
    }
}

// ---------------------------------------------------------------------------
// Per-(video,head,token) softmax over 12 frames; output tf32-rounded.
// ---------------------------------------------------------------------------
__global__ __launch_bounds__(256) void softmax_kernel(float* __restrict__ S, int ngroups)
{
    const int g = blockIdx.x * blockDim.x + threadIdx.x;
    if (g >= ngroups) return;
    float* p = S + (size_t)g * FR;
    float v[FR];
    float m = -3.0e38f;
#pragma unroll
    for (int i = 0; i < FR; i++) { v[i] = p[i]; m = fmaxf(m, v[i]); }
    float sum = 0.0f;
#pragma unroll
    for (int i = 0; i < FR; i++) { v[i] = __expf(v[i] - m); sum += v[i]; }
    const float inv = 1.0f / sum;
#pragma unroll
    for (int i = 0; i < FR; i++) p[i] = roundtf(v[i] * inv);
}

// ---------------------------------------------------------------------------
// Transpose V [768][512] -> Vt [512][768], tf32-rounded.
// ---------------------------------------------------------------------------
__global__ __launch_bounds__(256) void transpose_kernel(
    const float* __restrict__ in, float* __restrict__ out)
{
    __shared__ float t[32][33];
    const int x  = blockIdx.x * 32 + threadIdx.x;
    const int y0 = blockIdx.y * 32;
#pragma unroll
    for (int i = threadIdx.y; i < 32; i += 8)
        t[i][threadIdx.x] = in[(size_t)(y0 + i) * EMBED + x];
    __syncthreads();
    const int ox  = y0 + threadIdx.x;
    const int oy0 = blockIdx.x * 32;
#pragma unroll
    for (int i = threadIdx.y; i < 32; i += 8)
        out[(size_t)(oy0 + i) * VTOK + ox] = roundtf(t[threadIdx.x][i]);
}

// ---------------------------------------------------------------------------
extern "C" void kernel_launch(void* const* d_in, const int* in_sizes, int n_in,
                              void* d_out, int out_size)
{
    const float* text  = (const float*)d_in[0];
    const float* video = (const float*)d_in[1];
    const float* ln1_g = (const float*)d_in[2];
    const float* ln1_b = (const float*)d_in[3];
    const float* Wq = (const float*)d_in[4];
    const float* bq = (const float*)d_in[5];
    const float* Wk = (const float*)d_in[6];
    const float* bk = (const float*)d_in[7];
    const float* Wv = (const float*)d_in[8];
    const float* bv = (const float*)d_in[9];
    const float* Wo = (const float*)d_in[10];
    const float* bo = (const float*)d_in[11];
    const float* Wl = (const float*)d_in[12];
    const float* bl = (const float*)d_in[13];
    const float* ln2_g = (const float*)d_in[14];
    const float* ln2_b = (const float*)d_in[15];
    const float* ln3_g = (const float*)d_in[16];
    const float* ln3_b = (const float*)d_in[17];
    float* out = (float*)d_out;

    cudaFuncSetAttribute(mma_gemm,
        cudaFuncAttributeMaxDynamicSharedMemorySize, SMEM_BYTES);
    cudaFuncSetAttribute(proj3_gemm,
        cudaFuncAttributeMaxDynamicSharedMemorySize, SMEM_BYTES);

    float *tn, *vn, *q, *k, *v, *vt, *s, *attn, *opre, *o, *orr, *lin;
    float *wqr, *wkr, *wvr, *wor, *wlr;
    cudaGetSymbolAddress((void**)&tn,   g_tn);
    cudaGetSymbolAddress((void**)&vn,   g_vn);
    cudaGetSymbolAddress((void**)&q,    g_q);
    cudaGetSymbolAddress((void**)&k,    g_k);
    cudaGetSymbolAddress((void**)&v,    g_v);
    cudaGetSymbolAddress((void**)&vt,   g_vt);
    cudaGetSymbolAddress((void**)&s,    g_s);
    cudaGetSymbolAddress((void**)&attn, g_attn);
    cudaGetSymbolAddress((void**)&opre, g_opre);
    cudaGetSymbolAddress((void**)&o,    g_o);
    cudaGetSymbolAddress((void**)&orr,  g_or);
    cudaGetSymbolAddress((void**)&lin,  g_lin);
    cudaGetSymbolAddress((void**)&wqr,  g_wqr);
    cudaGetSymbolAddress((void**)&wkr,  g_wkr);
    cudaGetSymbolAddress((void**)&wvr,  g_wvr);
    cudaGetSymbolAddress((void**)&wor,  g_wor);
    cudaGetSymbolAddress((void**)&wlr,  g_wlr);

    // 0) round all weights to tf32 (parallel with LN1)
    roundw_kernel<<<dim3(EMBED*EMBED/1024, 5), 256>>>(
        Wq, Wk, Wv, Wo, Wl, wqr, wkr, wvr, wor, wlr);

    // 1) shared LN1 (outputs tf32-rounded; only feed GEMMs)
    ln_kernel<<<TTOK, 128>>>(text,  nullptr, ln1_g, ln1_b, tn, nullptr, 1);
    ln_kernel<<<VTOK, 128>>>(video, nullptr, ln1_g, ln1_b, vn, nullptr, 1);

    // 2) Q/K/V projections (q,k rounded; v full)
    proj3_gemm<<<dim3(4, 32, 3), 256, SMEM_BYTES>>>(
        tn, vn, wqr, wkr, wvr, bq, bk, bv, q, k, v);

    // 3) transpose V (rounds)
    transpose_kernel<<<dim3(16, 24), dim3(32, 8)>>>(v, vt);

    // 4) logits: S_h = Q_h @ K_h^T / 16 (full precision out; softmax rounds)
    mma_gemm<<<dim3(6, 32, 2), 256, SMEM_BYTES>>>(
        q, EMBED, HDIM, k, EMBED, HDIM,
        s, VTOK, (long)TTOK * VTOK, nullptr, 0, 1.0f / 16.0f, HDIM, 0);

    // 5) per-video frame softmax (rounds output)
    softmax_kernel<<<(HEADS * TTOK * NV + 255) / 256, 256>>>(s, HEADS * TTOK * NV);

    // 6) attn_h = P_h @ V_h / 64 (rounded out; feeds Wo GEMM)
    mma_gemm<<<dim3(2, 32, 2), 256, SMEM_BYTES>>>(
        s, VTOK, (long)TTOK * VTOK, vt, VTOK, (long)HDIM * VTOK,
        attn, EMBED, HDIM, nullptr, 0, 1.0f / 64.0f, VTOK, 1);

    // 7) output projection + LN2 (o full + rounded copy for Wl GEMM)
    mma_gemm<<<dim3(4, 32, 1), 256, SMEM_BYTES>>>(
        attn, EMBED, 0, wor, EMBED, 0, opre, EMBED, 0, bo, 0, 1.0f, EMBED, 0);
    ln_kernel<<<TTOK, 128>>>(opre, nullptr, ln2_g, ln2_b, o, orr, 0);

    // 8) linear + residual + LN3
    mma_gemm<<<dim3(4, 32, 1), 256, SMEM_BYTES>>>(
        orr, EMBED, 0, wlr, EMBED, 0, lin, EMBED, 0, bl, 0, 1.0f, EMBED, 0);
    ln_kernel<<<TTOK, 128>>>(o, lin, ln3_g, ln3_b, out, nullptr, 0);
}